// round 8
// baseline (speedup 1.0000x reference)
#include <cuda_runtime.h>

#define H 51
#define BB 16
#define NTHREADS 512
#define NPAIRS 231       // 3 regions x 77 row-pairs (regions padded 153->154)
#define NDOT 462         // 2 threads per pair (k-split)
#define KHALF 26         // k's per half (pad 51 -> 52)
#define HOFF 424         // half-1 k-range float offset: 26*16 + 8 -> 1696B ≡ 32 mod 128
#define HSTRIDE 840      // floats per h buffer: 52*16 + 8 gap
#define GROWS 462        // gbuf rows: 3 regions x 154
#define GPU 9            // gbuf pitch (ull)
#define GPF 18           // gbuf pitch (floats)
#define GR2 154
#define GR3 308
#define NPWP 408         // pair tasks per layer (51 u x 8 batch-pairs)

typedef unsigned long long ull;

#define FFMA2(d, a, b_) asm("fma.rn.f32x2 %0, %1, %2, %0;" : "+l"(d) : "l"(a), "l"(b_))
#define ADDF2(d, a)     asm("add.rn.f32x2 %0, %0, %1;"     : "+l"(d) : "l"(a))

__device__ __forceinline__ ull pack2(float lo, float hi) {
    ull r;
    asm("mov.b64 %0, {%1,%2};" : "=l"(r) : "f"(lo), "f"(hi));
    return r;
}
__device__ __forceinline__ float sigf(float v) {
    return __fdividef(1.0f, 1.0f + __expf(-v));
}
__device__ __forceinline__ float tanh_f(float v) {
    return 1.0f - __fdividef(2.0f, __expf(2.0f * v) + 1.0f);
}
// h element index with mid-gap: k<26 -> k*16, k>=26 -> k*16 + 8
__device__ __forceinline__ int hidx(int k) { return k * 16 + (k >= KHALF ? 8 : 0); }

__global__ __launch_bounds__(NTHREADS, 1)
void gru2_kernel(const float* __restrict__ input,
                 const float* __restrict__ w_ih1, const float* __restrict__ w_hh1,
                 const float* __restrict__ b_ih1, const float* __restrict__ b_hh1,
                 const float* __restrict__ w_ih2, const float* __restrict__ w_hh2,
                 const float* __restrict__ b_ih2, const float* __restrict__ b_hh2,
                 const float* __restrict__ w_lin, const float* __restrict__ b_lin,
                 float* __restrict__ out, int T, int F)
{
    extern __shared__ float sm[];
    float* hT1   = sm;                         // [2][HSTRIDE]  h1, k-major + gap
    float* hT2   = hT1 + 2 * HSTRIDE;          // [2][HSTRIDE]  h2
    ull*   gbufU = (ull*)(sm + 4 * HSTRIDE);   // [462][9]
    float* gbufF = (float*)gbufU;
    const float2* g2 = (const float2*)gbufF;
    float* tabs  = (float*)(gbufU + GROWS * GPU);  // w1r|w1z|w1n|c1r|c1z|c1n|wl (357) + 1 pad
    float* xbuf  = tabs + 7 * H + 1;           // [16], 8B-aligned
    float* oacc  = xbuf + BB;                  // [2][16], 8B-aligned

    const int tid = threadIdx.x;
    const int gb0 = blockIdx.x * BB;
    const int TOT = T + F;

    for (int i = tid; i < 4 * HSTRIDE; i += NTHREADS) sm[i] = 0.f;
    if (tid < H) {
        tabs[tid]         = __ldg(&w_ih1[tid]);
        tabs[H + tid]     = __ldg(&w_ih1[H + tid]);
        tabs[2 * H + tid] = __ldg(&w_ih1[2 * H + tid]);
        tabs[3 * H + tid] = __ldg(&b_ih1[tid]);
        tabs[4 * H + tid] = __ldg(&b_ih1[H + tid]);
        tabs[5 * H + tid] = __ldg(&b_ih1[2 * H + tid]);
        tabs[6 * H + tid] = __ldg(&w_lin[tid]);
    }
    if (tid < 2 * BB) oacc[tid] = 0.f;

    // Thread map: P = pair id (0..230), half = k-range half.
    // region = P/77 (0: whh1 x h1, 1: whh2 x h2, 2: wih2 x h1)
    const bool comp = (tid < NDOT);
    const int P    = comp ? (tid >> 1) : 0;
    const int half = tid & 1;
    const unsigned pmask = 0x3u << (tid & 30);

    const int region = P / 77;
    const int q      = P - region * 77;
    const int ra = 2 * q, rb = 2 * q + 1;
    const bool vB = (rb < 153);
    const float* base = (region == 0) ? w_hh1 : ((region == 1) ? w_hh2 : w_ih2);
    const float* bsrc = (region == 0) ? b_hh1 : ((region == 1) ? b_hh2 : b_ih2);
    const int hsel = (region == 1);

    float wA[KHALF], wB[KHALF];
    #pragma unroll
    for (int j = 0; j < KHALF; ++j) {
        int k = half * KHALF + j;
        wA[j] = (comp && k < H) ? __ldg(&base[ra * H + k]) : 0.f;
        wB[j] = (comp && vB && k < H) ? __ldg(&base[rb * H + k]) : 0.f;
    }
    float bA = comp ? __ldg(&bsrc[ra]) : 0.f;
    float bBv = (comp && vB) ? __ldg(&bsrc[rb]) : 0.f;
    const ull biasA = half ? 0ULL : pack2(bA, bA);
    const ull biasB = half ? 0ULL : pack2(bBv, bBv);
    const float blin = __ldg(&b_lin[0]);
    const int pxor = hsel ? 0 : 1;
    const float* hbase = hsel ? hT2 : hT1;
    const int hoff = half * HOFF;
    const int growA = region * 154 + ra;
    const int growB = region * 154 + rb;

    __syncthreads();

    for (int i = 0; i <= TOT; ++i) {
        const int par = i & 1;

        // ===== DOT STAGE: 2 rows/thread, batches chunked 8+8 =====
        if (comp) {
            const float* hp = hbase + ((par ^ pxor) * HSTRIDE) + hoff;
            #pragma unroll
            for (int c = 0; c < 2; ++c) {
                ull a0 = biasA, a1 = biasA, a2 = biasA, a3 = biasA;
                ull b0 = biasB, b1 = biasB, b2 = biasB, b3 = biasB;
                #pragma unroll
                for (int k = 0; k < KHALF; ++k) {
                    const ull wdA = pack2(wA[k], wA[k]);
                    const ull wdB = pack2(wB[k], wB[k]);
                    const ulonglong2* qk = (const ulonglong2*)(hp + k * 16) + 2 * c;
                    ulonglong2 u0 = qk[0], u1 = qk[1];
                    FFMA2(a0, wdA, u0.x); FFMA2(a1, wdA, u0.y);
                    FFMA2(a2, wdA, u1.x); FFMA2(a3, wdA, u1.y);
                    FFMA2(b0, wdB, u0.x); FFMA2(b1, wdB, u0.y);
                    FFMA2(b2, wdB, u1.x); FFMA2(b3, wdB, u1.y);
                }
                ull t;
                t = __shfl_xor_sync(pmask, a0, 1); ADDF2(a0, t);
                t = __shfl_xor_sync(pmask, a1, 1); ADDF2(a1, t);
                t = __shfl_xor_sync(pmask, a2, 1); ADDF2(a2, t);
                t = __shfl_xor_sync(pmask, a3, 1); ADDF2(a3, t);
                t = __shfl_xor_sync(pmask, b0, 1); ADDF2(b0, t);
                t = __shfl_xor_sync(pmask, b1, 1); ADDF2(b1, t);
                t = __shfl_xor_sync(pmask, b2, 1); ADDF2(b2, t);
                t = __shfl_xor_sync(pmask, b3, 1); ADDF2(b3, t);
                if (!half) {
                    ull* goA = gbufU + growA * GPU + 4 * c;
                    ull* goB = gbufU + growB * GPU + 4 * c;
                    goA[0] = a0; goA[1] = a1; goA[2] = a2; goA[3] = a3;
                    goB[0] = b0; goB[1] = b1; goB[2] = b2; goB[3] = b3;
                }
            }
        } else {
            int j = tid - NDOT;
            if (j < BB) {
                if (i >= 2) out[(size_t)(gb0 + j) * TOT + (i - 2)] = oacc[((i - 1) & 1) * BB + j] + blin;
                oacc[par * BB + j] = 0.f;
                if (i < T) xbuf[j] = __ldg(&input[(size_t)(gb0 + j) * T + i]);
            }
        }
        __syncthreads();

        // ===== POINTWISE STAGE (batch-pair tasks) =====
        float* oa  = oacc + par * BB;
        float* h2c = hT2 + par * HSTRIDE;          // h2[i-2]
        float* h2n = hT2 + (par ^ 1) * HSTRIDE;    // h2[i-1]
        float* h1c = hT1 + (par ^ 1) * HSTRIDE;    // h1[i-1]
        float* h1n = hT1 + par * HSTRIDE;          // h1[i]

        if (i < T) {
            for (int j = tid; j < 2 * NPWP; j += NTHREADS) {
                if (j < NPWP) {
                    if (i > 0) {
                        int u = j >> 3, bp = j & 7;
                        int hx = hidx(u) + 2 * bp;
                        float2 dir = g2[(GR3 + u) * GPU + bp];
                        float2 diz = g2[(GR3 + 51 + u) * GPU + bp];
                        float2 din = g2[(GR3 + 102 + u) * GPU + bp];
                        float2 d2r = g2[(GR2 + u) * GPU + bp];
                        float2 d2z = g2[(GR2 + 51 + u) * GPU + bp];
                        float2 d2n = g2[(GR2 + 102 + u) * GPU + bp];
                        float2 hold = *(const float2*)(h2c + hx);
                        float wl = tabs[6 * H + u];
                        float r0 = sigf(dir.x + d2r.x), r1 = sigf(dir.y + d2r.y);
                        float z0 = sigf(diz.x + d2z.x), z1 = sigf(diz.y + d2z.y);
                        float n0 = tanh_f(fmaf(r0, d2n.x, din.x));
                        float n1 = tanh_f(fmaf(r1, d2n.y, din.y));
                        float h0 = n0 + z0 * (hold.x - n0);
                        float h1 = n1 + z1 * (hold.y - n1);
                        *(float2*)(h2n + hx) = make_float2(h0, h1);
                        atomicAdd(&oa[2 * bp],     wl * h0);
                        atomicAdd(&oa[2 * bp + 1], wl * h1);
                    }
                } else {
                    int jj = j - NPWP;
                    int u = jj >> 3, bp = jj & 7;
                    int hx = hidx(u) + 2 * bp;
                    float2 x2 = *(const float2*)(xbuf + 2 * bp);
                    float2 ar = g2[u * GPU + bp];
                    float2 az = g2[(51 + u) * GPU + bp];
                    float2 an = g2[(102 + u) * GPU + bp];
                    float2 hold = *(const float2*)(h1c + hx);
                    float w1r = tabs[u], w1z = tabs[H + u], w1n = tabs[2 * H + u];
                    float c1r = tabs[3 * H + u], c1z = tabs[4 * H + u], c1n = tabs[5 * H + u];
                    float r0 = sigf(fmaf(x2.x, w1r, c1r) + ar.x);
                    float r1 = sigf(fmaf(x2.y, w1r, c1r) + ar.y);
                    float z0 = sigf(fmaf(x2.x, w1z, c1z) + az.x);
                    float z1 = sigf(fmaf(x2.y, w1z, c1z) + az.y);
                    float n0 = tanh_f(fmaf(x2.x, w1n, c1n) + r0 * an.x);
                    float n1 = tanh_f(fmaf(x2.y, w1n, c1n) + r1 * an.y);
                    float h0 = n0 + z0 * (hold.x - n0);
                    float h1 = n1 + z1 * (hold.y - n1);
                    *(float2*)(h1n + hx) = make_float2(h0, h1);
                }
            }
            __syncthreads();
        } else {
            for (int j = tid; j < NPWP; j += NTHREADS) {
                int u = j >> 3, bp = j & 7;
                int hx = hidx(u) + 2 * bp;
                float2 dir = g2[(GR3 + u) * GPU + bp];
                float2 diz = g2[(GR3 + 51 + u) * GPU + bp];
                float2 din = g2[(GR3 + 102 + u) * GPU + bp];
                float2 d2r = g2[(GR2 + u) * GPU + bp];
                float2 d2z = g2[(GR2 + 51 + u) * GPU + bp];
                float2 d2n = g2[(GR2 + 102 + u) * GPU + bp];
                float2 hold = *(const float2*)(h2c + hx);
                float wl = tabs[6 * H + u];
                float r0 = sigf(dir.x + d2r.x), r1 = sigf(dir.y + d2r.y);
                float z0 = sigf(diz.x + d2z.x), z1 = sigf(diz.y + d2z.y);
                float n0 = tanh_f(fmaf(r0, d2n.x, din.x));
                float n1 = tanh_f(fmaf(r1, d2n.y, din.y));
                float h0 = n0 + z0 * (hold.x - n0);
                float h1 = n1 + z1 * (hold.y - n1);
                *(float2*)(h2n + hx) = make_float2(h0, h1);
                atomicAdd(&oa[2 * bp],     wl * h0);
                atomicAdd(&oa[2 * bp + 1], wl * h1);
            }
            __syncthreads();
            for (int j = tid; j < NPWP; j += NTHREADS) {
                int u = j >> 3, bp = j & 7;
                int hx = hidx(u) + 2 * bp;
                float2 x2 = *(const float2*)(oa + 2 * bp);
                x2.x += blin; x2.y += blin;
                float2 ar = g2[u * GPU + bp];
                float2 az = g2[(51 + u) * GPU + bp];
                float2 an = g2[(102 + u) * GPU + bp];
                float2 hold = *(const float2*)(h1c + hx);
                float w1r = tabs[u], w1z = tabs[H + u], w1n = tabs[2 * H + u];
                float c1r = tabs[3 * H + u], c1z = tabs[4 * H + u], c1n = tabs[5 * H + u];
                float r0 = sigf(fmaf(x2.x, w1r, c1r) + ar.x);
                float r1 = sigf(fmaf(x2.y, w1r, c1r) + ar.y);
                float z0 = sigf(fmaf(x2.x, w1z, c1z) + az.x);
                float z1 = sigf(fmaf(x2.y, w1z, c1z) + az.y);
                float n0 = tanh_f(fmaf(x2.x, w1n, c1n) + r0 * an.x);
                float n1 = tanh_f(fmaf(x2.y, w1n, c1n) + r1 * an.y);
                float h0 = n0 + z0 * (hold.x - n0);
                float h1 = n1 + z1 * (hold.y - n1);
                *(float2*)(h1n + hx) = make_float2(h0, h1);
            }
            __syncthreads();
        }
    }

    if (tid < BB)
        out[(size_t)(gb0 + tid) * TOT + (TOT - 1)] = oacc[(TOT & 1) * BB + tid] + blin;
}

extern "C" void kernel_launch(void* const* d_in, const int* in_sizes, int n_in,
                              void* d_out, int out_size) {
    const float* input = (const float*)d_in[0];
    const float* w_ih1 = (const float*)d_in[2];
    const float* w_hh1 = (const float*)d_in[3];
    const float* b_ih1 = (const float*)d_in[4];
    const float* b_hh1 = (const float*)d_in[5];
    const float* w_ih2 = (const float*)d_in[6];
    const float* w_hh2 = (const float*)d_in[7];
    const float* b_ih2 = (const float*)d_in[8];
    const float* b_hh2 = (const float*)d_in[9];
    const float* w_lin = (const float*)d_in[10];
    const float* b_lin = (const float*)d_in[11];

    const int B   = 2048;
    const int T   = in_sizes[0] / B;
    const int TOT = out_size / B;
    const int F   = TOT - T;

    size_t smem = (size_t)(4 * HSTRIDE * 4 + GROWS * GPU * 8 + (7 * H + 1 + BB + 2 * BB) * 4);
    cudaFuncSetAttribute(gru2_kernel, cudaFuncAttributeMaxDynamicSharedMemorySize, (int)smem);

    gru2_kernel<<<B / BB, NTHREADS, smem>>>(
        input, w_ih1, w_hh1, b_ih1, b_hh1,
        w_ih2, w_hh2, b_ih2, b_hh2,
        w_lin, b_lin, (float*)d_out, T, F);
}